// round 1
// baseline (speedup 1.0000x reference)
#include <cuda_runtime.h>
#include <math.h>

#define B_ 4
#define H_ 8
#define S_ 2048
#define D_ 16
#define QT 16           // queries per CTA
#define KT 128          // key tile
#define SSTRIDE 2064    // padded score row stride (floats): 2048+16 -> conflict-free
#define TSTRIDE 20      // padded K/V tile row stride (floats): 16+4
#define NTHREADS 512

// smem: scores[QT][SSTRIDE] + tile[KT][TSTRIDE]
#define SMEM_FLOATS (QT * SSTRIDE + KT * TSTRIDE)
#define SMEM_BYTES  (SMEM_FLOATS * 4)

__global__ void __launch_bounds__(NTHREADS, 1)
sdpa_kernel(const float* __restrict__ Q, const float* __restrict__ K,
            const float* __restrict__ V, const int* __restrict__ mask,
            float* __restrict__ ctx_out, float* __restrict__ attn_out)
{
    extern __shared__ float sm[];
    float* scores = sm;                       // [QT][SSTRIDE]
    float* tile   = sm + QT * SSTRIDE;        // [KT][TSTRIDE]

    const int h  = blockIdx.x;
    const int qt = blockIdx.y;
    const int b  = blockIdx.z;
    const int bh = b * H_ + h;

    const float* Qb = Q + (size_t)bh * S_ * D_;
    const float* Kb = K + (size_t)bh * S_ * D_;
    const float* Vb = V + (size_t)bh * S_ * D_;
    const int*   Mb = mask + (size_t)b * S_ * S_;

    const int tid  = threadIdx.x;
    const int q    = tid >> 5;      // warp id == query row in tile
    const int lane = tid & 31;
    const int qg   = qt * QT + q;   // global query index

    // Q row into registers (all lanes load same row -> broadcast)
    const float4* Qr = reinterpret_cast<const float4*>(Qb + (size_t)qg * D_);
    const float4 q0 = Qr[0], q1 = Qr[1], q2 = Qr[2], q3 = Qr[3];

    float* srow = &scores[q * SSTRIDE];
    const int* mrow = Mb + (size_t)qg * S_;

    // ---------------- Phase A: scores = mask ? -1e9 : (Q.K)/4 ----------------
    for (int kt = 0; kt < S_ / KT; ++kt) {
        const int kbase = kt * KT;
        __syncthreads();  // protect tile buffer from previous iteration's readers
        {
            // 128 rows x 16 floats = 512 float4 loads; one per thread, coalesced
            int r = tid >> 2, c = tid & 3;
            float4 v = reinterpret_cast<const float4*>(Kb + (size_t)(kbase + r) * D_)[c];
            *reinterpret_cast<float4*>(&tile[r * TSTRIDE + c * 4]) = v;
        }
        __syncthreads();
        #pragma unroll
        for (int jj = 0; jj < KT / 32; ++jj) {
            const int kl = jj * 32 + lane;
            const float4* kr = reinterpret_cast<const float4*>(&tile[kl * TSTRIDE]);
            const float4 k0 = kr[0], k1 = kr[1], k2 = kr[2], k3 = kr[3];
            float dot = q0.x * k0.x + q0.y * k0.y + q0.z * k0.z + q0.w * k0.w
                      + q1.x * k1.x + q1.y * k1.y + q1.z * k1.z + q1.w * k1.w
                      + q2.x * k2.x + q2.y * k2.y + q2.z * k2.z + q2.w * k2.w
                      + q3.x * k3.x + q3.y * k3.y + q3.z * k3.z + q3.w * k3.w;
            const int m = mrow[kbase + kl];
            srow[kbase + kl] = m ? -1e9f : dot * 0.25f;
        }
    }
    __syncthreads();

    // ---------------- Phase B: softmax (per warp = per query row) ----------------
    float mx = -INFINITY;
    #pragma unroll 8
    for (int j = 0; j < S_ / 32; ++j)
        mx = fmaxf(mx, srow[j * 32 + lane]);
    #pragma unroll
    for (int o = 16; o > 0; o >>= 1)
        mx = fmaxf(mx, __shfl_xor_sync(0xffffffffu, mx, o));

    float sum = 0.0f;
    #pragma unroll 8
    for (int j = 0; j < S_ / 32; ++j) {
        const float e = __expf(srow[j * 32 + lane] - mx);
        srow[j * 32 + lane] = e;
        sum += e;
    }
    #pragma unroll
    for (int o = 16; o > 0; o >>= 1)
        sum += __shfl_xor_sync(0xffffffffu, sum, o);
    const float inv = 1.0f / sum;

    // ---------------- Phase C: write attn + context = attn @ V ----------------
    float c[D_];
    #pragma unroll
    for (int d = 0; d < D_; ++d) c[d] = 0.0f;

    float* arow = attn_out ? attn_out + ((size_t)bh * S_ + qg) * S_ : nullptr;

    for (int kt = 0; kt < S_ / KT; ++kt) {
        const int kbase = kt * KT;
        __syncthreads();
        {
            int r = tid >> 2, cc = tid & 3;
            float4 v = reinterpret_cast<const float4*>(Vb + (size_t)(kbase + r) * D_)[cc];
            *reinterpret_cast<float4*>(&tile[r * TSTRIDE + cc * 4]) = v;
        }
        __syncthreads();
        #pragma unroll
        for (int jj = 0; jj < KT / 32; ++jj) {
            const int kl = jj * 32 + lane;
            const float a = srow[kbase + kl] * inv;
            if (arow) arow[kbase + kl] = a;
            const float4* vr = reinterpret_cast<const float4*>(&tile[kl * TSTRIDE]);
            const float4 v0 = vr[0], v1 = vr[1], v2 = vr[2], v3 = vr[3];
            c[0]  += a * v0.x;  c[1]  += a * v0.y;  c[2]  += a * v0.z;  c[3]  += a * v0.w;
            c[4]  += a * v1.x;  c[5]  += a * v1.y;  c[6]  += a * v1.z;  c[7]  += a * v1.w;
            c[8]  += a * v2.x;  c[9]  += a * v2.y;  c[10] += a * v2.z;  c[11] += a * v2.w;
            c[12] += a * v3.x;  c[13] += a * v3.y;  c[14] += a * v3.z;  c[15] += a * v3.w;
        }
    }

    // warp-reduce the 16 context accumulators
    #pragma unroll
    for (int o = 16; o > 0; o >>= 1) {
        #pragma unroll
        for (int d = 0; d < D_; ++d)
            c[d] += __shfl_xor_sync(0xffffffffu, c[d], o);
    }

    if (ctx_out && lane < D_) {
        // pick c[lane] without dynamic register indexing
        float out = 0.0f;
        #pragma unroll
        for (int d = 0; d < D_; ++d)
            if (lane == d) out = c[d];
        ctx_out[((size_t)bh * S_ + qg) * D_ + lane] = out;
    }
}

extern "C" void kernel_launch(void* const* d_in, const int* in_sizes, int n_in,
                              void* d_out, int out_size)
{
    const float* Q    = (const float*)d_in[0];
    const float* K    = (const float*)d_in[1];
    const float* V    = (const float*)d_in[2];
    const int*   mask = (const int*)d_in[3];

    const long long CTX = (long long)B_ * H_ * S_ * D_;        // 1,048,576
    const long long ATT = (long long)B_ * H_ * S_ * S_;        // 134,217,728

    float* out  = (float*)d_out;
    float* ctx  = nullptr;
    float* attn = nullptr;
    if ((long long)out_size == CTX + ATT)      { ctx = out; attn = out + CTX; }
    else if ((long long)out_size == ATT)       { attn = out; }
    else if ((long long)out_size == CTX)       { ctx = out; }
    else                                       { ctx = out; if ((long long)out_size >= CTX + ATT) attn = out + CTX; }

    cudaFuncSetAttribute(sdpa_kernel, cudaFuncAttributeMaxDynamicSharedMemorySize, SMEM_BYTES);

    dim3 grid(H_, S_ / QT, B_);   // heads fastest -> mask rows reused in L2 across the 8 heads
    sdpa_kernel<<<grid, NTHREADS, SMEM_BYTES>>>(Q, K, V, mask, ctx, attn);
}

// round 2
// speedup vs baseline: 1.2765x; 1.2765x over previous
#include <cuda_runtime.h>
#include <math.h>

#define B_ 4
#define H_ 8
#define S_ 2048
#define D_ 16
#define QT 16           // queries per CTA
#define NT 512          // threads
#define SSTRIDE 2064    // padded score row stride (floats)
#define TSTR 264        // padded transposed-V tile row stride (floats): 256 keys + 8 pad
#define HALF_KEYS 1024

// SMEM layout (floats)
#define OFF_SCORES 0
#define OFF_TILE   (QT * SSTRIDE)                 // tileT[D_][TSTR]
#define OFF_SQ     (OFF_TILE + D_ * TSTR)         // sQ[256]
#define OFF_SINV   (OFF_SQ + 256)                 // sinv[16]
#define OFF_SCTX   (OFF_SINV + 16)                // sctx[2][16][16]
#define SMEM_FLOATS (OFF_SCTX + 512)
#define SMEM_BYTES  (SMEM_FLOATS * 4)

__global__ void __launch_bounds__(NT, 1)
sdpa_kernel(const float* __restrict__ Q, const float* __restrict__ K,
            const float* __restrict__ V, const int* __restrict__ mask,
            float* __restrict__ ctx_out, float* __restrict__ attn_out)
{
    extern __shared__ float sm[];
    float* scores = sm + OFF_SCORES;   // [QT][SSTRIDE]
    float* tileT  = sm + OFF_TILE;     // [D_][TSTR]  (transposed V, 2 blocks of 128 keys)
    float* sQ     = sm + OFF_SQ;       // [QT*D_]
    float* sinv   = sm + OFF_SINV;     // [QT]
    float* sctx   = sm + OFF_SCTX;     // [2][QT][D_]

    const int h  = blockIdx.x;
    const int qt = blockIdx.y;
    const int b  = blockIdx.z;
    const int bh = b * H_ + h;

    const float* Qb = Q + (size_t)bh * S_ * D_;
    const float* Kb = K + (size_t)bh * S_ * D_;
    const float* Vb = V + (size_t)bh * S_ * D_;
    const int*   Mb = mask + (size_t)b * S_ * S_;

    const int tid  = threadIdx.x;
    const int lane = tid & 31;
    const int w    = tid >> 5;
    const int q0base = qt * QT;

    // ---- Load Q tile (256 consecutive floats) ----
    if (tid < 256) sQ[tid] = Qb[(size_t)qt * 256 + tid];
    __syncthreads();

    // ================= Phase A: scores = mask ? -1e9 : (Q.K)/4 =================
    // thread-per-key: K row in registers, Q via broadcast LDS (tiny bandwidth)
    #pragma unroll 1
    for (int pass = 0; pass < 4; ++pass) {
        const int k = pass * NT + tid;
        const float4* Kr = reinterpret_cast<const float4*>(Kb + (size_t)k * D_);
        const float4 k0 = Kr[0], k1 = Kr[1], k2 = Kr[2], k3 = Kr[3];
        #pragma unroll
        for (int q = 0; q < QT; ++q) {
            const float4* Qs = reinterpret_cast<const float4*>(sQ + q * D_);
            const float4 a0 = Qs[0], a1 = Qs[1], a2 = Qs[2], a3 = Qs[3];
            float d0 = a0.x * k0.x + a0.y * k0.y + a0.z * k0.z + a0.w * k0.w;
            float d1 = a1.x * k1.x + a1.y * k1.y + a1.z * k1.z + a1.w * k1.w;
            float d2 = a2.x * k2.x + a2.y * k2.y + a2.z * k2.z + a2.w * k2.w;
            float d3 = a3.x * k3.x + a3.y * k3.y + a3.z * k3.z + a3.w * k3.w;
            const float dot = (d0 + d1) + (d2 + d3);
            const int m = Mb[(size_t)(q0base + q) * S_ + k];
            scores[q * SSTRIDE + k] = m ? -1e9f : dot * 0.25f;
        }
    }
    __syncthreads();

    // ================= Phase B: softmax over each score row (warp = query) =====
    {
        float* srow = scores + w * SSTRIDE;
        float mx = -INFINITY;
        #pragma unroll
        for (int j = 0; j < S_ / 128; ++j) {
            const float4 s = *reinterpret_cast<const float4*>(srow + j * 128 + lane * 4);
            mx = fmaxf(mx, fmaxf(fmaxf(s.x, s.y), fmaxf(s.z, s.w)));
        }
        #pragma unroll
        for (int o = 16; o > 0; o >>= 1)
            mx = fmaxf(mx, __shfl_xor_sync(0xffffffffu, mx, o));

        float sum = 0.0f;
        #pragma unroll
        for (int j = 0; j < S_ / 128; ++j) {
            float4 s = *reinterpret_cast<float4*>(srow + j * 128 + lane * 4);
            s.x = __expf(s.x - mx);
            s.y = __expf(s.y - mx);
            s.z = __expf(s.z - mx);
            s.w = __expf(s.w - mx);
            sum += (s.x + s.y) + (s.z + s.w);
            *reinterpret_cast<float4*>(srow + j * 128 + lane * 4) = s;
        }
        #pragma unroll
        for (int o = 16; o > 0; o >>= 1)
            sum += __shfl_xor_sync(0xffffffffu, sum, o);
        if (lane == 0) sinv[w] = 1.0f / sum;
    }
    __syncthreads();

    // ================= Phase C: attn write + context = attn @ V ================
    // warp = (query pair, key half); V tile transposed & conflict-free.
    const int qa = (w & 7) * 2, qb = qa + 1;
    const int khalf = w >> 3;
    const float inva = sinv[qa];
    const float invb = sinv[qb];

    float ca[D_], cb[D_];
    #pragma unroll
    for (int d = 0; d < D_; ++d) { ca[d] = 0.0f; cb[d] = 0.0f; }

    float* arowA = attn_out ? attn_out + ((size_t)bh * S_ + q0base + qa) * S_ : nullptr;
    float* arowB = attn_out ? attn_out + ((size_t)bh * S_ + q0base + qb) * S_ : nullptr;
    const float* srA = scores + qa * SSTRIDE;
    const float* srB = scores + qb * SSTRIDE;

    const int kk0 = tid & 127;      // tile-load key-in-block
    const int grp = tid >> 7;       // tile-load d-group (0..3)

    #pragma unroll 1
    for (int it = 0; it < 8; ++it) {
        __syncthreads();   // previous iteration's readers done with tileT
        {
            const int kA = it * 128 + kk0;                // block 0 keys
            const int kB = HALF_KEYS + it * 128 + kk0;    // block 1 keys
            const float4 vA = *reinterpret_cast<const float4*>(Vb + (size_t)kA * D_ + grp * 4);
            const float4 vB = *reinterpret_cast<const float4*>(Vb + (size_t)kB * D_ + grp * 4);
            tileT[(grp * 4 + 0) * TSTR + kk0] = vA.x;
            tileT[(grp * 4 + 1) * TSTR + kk0] = vA.y;
            tileT[(grp * 4 + 2) * TSTR + kk0] = vA.z;
            tileT[(grp * 4 + 3) * TSTR + kk0] = vA.w;
            tileT[(grp * 4 + 0) * TSTR + 128 + kk0] = vB.x;
            tileT[(grp * 4 + 1) * TSTR + 128 + kk0] = vB.y;
            tileT[(grp * 4 + 2) * TSTR + 128 + kk0] = vB.z;
            tileT[(grp * 4 + 3) * TSTR + 128 + kk0] = vB.w;
        }
        __syncthreads();

        const int kglob = khalf * HALF_KEYS + it * 128 + lane * 4;  // global key of this lane's 4
        const float4 ea = *reinterpret_cast<const float4*>(srA + kglob);
        const float4 eb = *reinterpret_cast<const float4*>(srB + kglob);
        float4 aa, ab;
        aa.x = ea.x * inva; aa.y = ea.y * inva; aa.z = ea.z * inva; aa.w = ea.w * inva;
        ab.x = eb.x * invb; ab.y = eb.y * invb; ab.z = eb.z * invb; ab.w = eb.w * invb;
        if (arowA) *reinterpret_cast<float4*>(arowA + kglob) = aa;
        if (arowB) *reinterpret_cast<float4*>(arowB + kglob) = ab;

        const int col = khalf * 128 + lane * 4;
        #pragma unroll
        for (int d = 0; d < D_; ++d) {
            const float4 v = *reinterpret_cast<const float4*>(tileT + d * TSTR + col);
            ca[d] += aa.x * v.x + aa.y * v.y + aa.z * v.z + aa.w * v.w;
            cb[d] += ab.x * v.x + ab.y * v.y + ab.z * v.z + ab.w * v.w;
        }
    }

    // lane-reduce the per-lane partial contexts
    #pragma unroll
    for (int o = 16; o > 0; o >>= 1) {
        #pragma unroll
        for (int d = 0; d < D_; ++d) {
            ca[d] += __shfl_xor_sync(0xffffffffu, ca[d], o);
            cb[d] += __shfl_xor_sync(0xffffffffu, cb[d], o);
        }
    }
    if (lane < D_) {
        float oa = 0.0f, ob = 0.0f;
        #pragma unroll
        for (int d = 0; d < D_; ++d)
            if (lane == d) { oa = ca[d]; ob = cb[d]; }
        sctx[(khalf * QT + qa) * D_ + lane] = oa;
        sctx[(khalf * QT + qb) * D_ + lane] = ob;
    }
    __syncthreads();

    // combine the two key-halves and store the ctx tile (256 consecutive floats)
    if (ctx_out && tid < 256) {
        const float v = sctx[tid] + sctx[256 + tid];
        ctx_out[(size_t)bh * S_ * D_ + (size_t)q0base * D_ + tid] = v;
    }
}

extern "C" void kernel_launch(void* const* d_in, const int* in_sizes, int n_in,
                              void* d_out, int out_size)
{
    const float* Q    = (const float*)d_in[0];
    const float* K    = (const float*)d_in[1];
    const float* V    = (const float*)d_in[2];
    const int*   mask = (const int*)d_in[3];

    const long long CTX = (long long)B_ * H_ * S_ * D_;        // 1,048,576
    const long long ATT = (long long)B_ * H_ * S_ * S_;        // 134,217,728

    float* out  = (float*)d_out;
    float* ctx  = nullptr;
    float* attn = nullptr;
    if ((long long)out_size == CTX + ATT)      { ctx = out; attn = out + CTX; }
    else if ((long long)out_size == ATT)       { attn = out; }
    else if ((long long)out_size == CTX)       { ctx = out; }
    else                                       { ctx = out; if ((long long)out_size >= CTX + ATT) attn = out + CTX; }

    cudaFuncSetAttribute(sdpa_kernel, cudaFuncAttributeMaxDynamicSharedMemorySize, SMEM_BYTES);

    dim3 grid(H_, S_ / QT, B_);   // heads fastest -> mask rows reused in L2 across the 8 heads
    sdpa_kernel<<<grid, NT, SMEM_BYTES>>>(Q, K, V, mask, ctx, attn);
}